// round 12
// baseline (speedup 1.0000x reference)
#include <cuda_runtime.h>
#include <cuda_bf16.h>
#include <math.h>
#include <stdint.h>

#define B_      2
#define N_      4096
#define C_      256
#define H_      4
#define D_      64
#define MTOT    (B_*N_)        // 8192
// Q pre-scale: (1/8) * log2(e)  -> softmax numerator = exp2(S')
#define QSCALE_ 0.18033688011112042f

// Scratch (device globals; allocation-free)
__device__ __nv_bfloat16 g_whi[4][C_*C_], g_wlo[4][C_*C_];
__device__ __nv_bfloat16 g_qhi[MTOT*C_], g_qlo[MTOT*C_];   // [bh][n][d], Q pre-scaled
__device__ __nv_bfloat16 g_khi[MTOT*C_], g_klo[MTOT*C_];   // [bh][n][d]
__device__ __nv_bfloat16 g_vhi[MTOT*C_], g_vlo[MTOT*C_];   // [bh][n][d]
__device__ __nv_bfloat16 g_att[MTOT*C_];                   // [B*N][C] bf16 (exact)

// ---------------------------------------------------------------------------
// helpers
// ---------------------------------------------------------------------------
__device__ __forceinline__ void mma_bf16(float c[4],
    uint32_t a0, uint32_t a1, uint32_t a2, uint32_t a3,
    uint32_t b0, uint32_t b1)
{
    asm volatile(
        "mma.sync.aligned.m16n8k16.row.col.f32.bf16.bf16.f32 "
        "{%0,%1,%2,%3}, {%4,%5,%6,%7}, {%8,%9}, {%0,%1,%2,%3};"
        : "+f"(c[0]), "+f"(c[1]), "+f"(c[2]), "+f"(c[3])
        : "r"(a0), "r"(a1), "r"(a2), "r"(a3), "r"(b0), "r"(b1));
}
__device__ __forceinline__ void ldmx4(uint32_t r[4], const void* p)
{
    uint32_t a = (uint32_t)__cvta_generic_to_shared(p);
    asm volatile("ldmatrix.sync.aligned.m8n8.x4.shared.b16 {%0,%1,%2,%3}, [%4];"
                 : "=r"(r[0]), "=r"(r[1]), "=r"(r[2]), "=r"(r[3]) : "r"(a));
}
__device__ __forceinline__ void ldmx4a(uint32_t r[4], uint32_t a)
{
    asm volatile("ldmatrix.sync.aligned.m8n8.x4.shared.b16 {%0,%1,%2,%3}, [%4];"
                 : "=r"(r[0]), "=r"(r[1]), "=r"(r[2]), "=r"(r[3]) : "r"(a));
}
__device__ __forceinline__ void ldmx4ta(uint32_t r[4], uint32_t a)
{
    asm volatile("ldmatrix.sync.aligned.m8n8.x4.trans.shared.b16 {%0,%1,%2,%3}, [%4];"
                 : "=r"(r[0]), "=r"(r[1]), "=r"(r[2]), "=r"(r[3]) : "r"(a));
}
__device__ __forceinline__ uint32_t pack_bf2(float a, float b)
{
    __nv_bfloat162 t = __floats2bfloat162_rn(a, b);
    return *(uint32_t*)&t;
}
__device__ __forceinline__ void cpa16(uint32_t dst, const void* src)
{
    asm volatile("cp.async.cg.shared.global [%0], [%1], 16;" :: "r"(dst), "l"(src));
}
__device__ __forceinline__ void cpa_commit()
{
    asm volatile("cp.async.commit_group;" ::: "memory");
}
template<int N>
__device__ __forceinline__ void cpa_wait()
{
    asm volatile("cp.async.wait_group %0;" :: "n"(N) : "memory");
}
__device__ __forceinline__ void split2(float a, float b, uint32_t& hi, uint32_t& lo)
{
    hi = pack_bf2(a, b);
    __nv_bfloat162 t = *(__nv_bfloat162*)&hi;
    float2 f = __bfloat1622float2(t);
    lo = pack_bf2(a - f.x, b - f.y);
}
__device__ __forceinline__ float ex2(float x)
{
    float r;
    asm("ex2.approx.f32 %0, %1;" : "=f"(r) : "f"(x));
    return r;
}

// ---------------------------------------------------------------------------
// split weights fp32 -> bf16 hi/lo (all 4 in one launch)
// ---------------------------------------------------------------------------
__global__ void split_w4(const float* __restrict__ w0, const float* __restrict__ w1,
                         const float* __restrict__ w2, const float* __restrict__ w3,
                         __nv_bfloat16* __restrict__ hi, __nv_bfloat16* __restrict__ lo)
{
    const int p = blockIdx.y;
    const float* src = (p == 0) ? w0 : (p == 1) ? w1 : (p == 2) ? w2 : w3;
    int i = blockIdx.x * blockDim.x + threadIdx.x;
    if (i >= C_*C_/4) return;
    float4 v = ((const float4*)src)[i];
    uint32_t h01, l01, h23, l23;
    split2(v.x, v.y, h01, l01);
    split2(v.z, v.w, h23, l23);
    ((uint2*)(hi + (size_t)p * C_ * C_))[i] = make_uint2(h01, h23);
    ((uint2*)(lo + (size_t)p * C_ * C_))[i] = make_uint2(l01, l23);
}

// ---------------------------------------------------------------------------
// Fused Q/K/V projection (3-term split bf16 MMA), NT. x clip+split inline.
// ---------------------------------------------------------------------------
#define GARR 4608   // elements per [64][72] array

__global__ __launch_bounds__(128, 3)
void gemm_qkv(const float* __restrict__ x,
              const __nv_bfloat16* __restrict__ Whi, const __nv_bfloat16* __restrict__ Wlo,
              const float* __restrict__ bq, const float* __restrict__ bk,
              const float* __restrict__ bv,
              __nv_bfloat16* __restrict__ qhi, __nv_bfloat16* __restrict__ qlo,
              __nv_bfloat16* __restrict__ khi, __nv_bfloat16* __restrict__ klo,
              __nv_bfloat16* __restrict__ vhi, __nv_bfloat16* __restrict__ vlo)
{
    extern __shared__ __align__(16) __nv_bfloat16 smg[];
    __nv_bfloat16* Ah = smg;
    __nv_bfloat16* Al = smg + GARR;

    const int tid  = threadIdx.x;
    const int lane = tid & 31;
    const int wid  = tid >> 5;
    const int wr   = wid * 16;
    const int m0   = blockIdx.x * 64;
    const int n0   = blockIdx.y * 64;

    const int grp = lane >> 3, rr = lane & 7;
    const int k_rofs = ((grp & 2) ? 8 : 0) + rr;
    const int k_cofs = (grp & 1) ? 8 : 0;

    float acc[3][8][4];
    #pragma unroll
    for (int p = 0; p < 3; p++)
        #pragma unroll
        for (int i = 0; i < 8; i++)
            { acc[p][i][0]=0.f; acc[p][i][1]=0.f; acc[p][i][2]=0.f; acc[p][i][3]=0.f; }

    for (int kt0 = 0; kt0 < 4; kt0++) {
        const int k0 = kt0 * 64;
        __syncthreads();
        #pragma unroll
        for (int it = 0; it < 4; it++) {
            const int idx = it * 128 + tid;
            const int r = idx >> 3, c8 = (idx & 7) * 8;
            {
                const float* xp = &x[(size_t)(m0 + r) * C_ + k0 + c8];
                float4 v0 = *(const float4*)xp;
                float4 v1 = *(const float4*)(xp + 4);
                v0.x = fminf(fmaxf(v0.x, -10000.f), 10000.f);
                v0.y = fminf(fmaxf(v0.y, -10000.f), 10000.f);
                v0.z = fminf(fmaxf(v0.z, -10000.f), 10000.f);
                v0.w = fminf(fmaxf(v0.w, -10000.f), 10000.f);
                v1.x = fminf(fmaxf(v1.x, -10000.f), 10000.f);
                v1.y = fminf(fmaxf(v1.y, -10000.f), 10000.f);
                v1.z = fminf(fmaxf(v1.z, -10000.f), 10000.f);
                v1.w = fminf(fmaxf(v1.w, -10000.f), 10000.f);
                uint32_t h0, l0, h1, l1, h2, l2, h3, l3;
                split2(v0.x, v0.y, h0, l0);
                split2(v0.z, v0.w, h1, l1);
                split2(v1.x, v1.y, h2, l2);
                split2(v1.z, v1.w, h3, l3);
                *(uint4*)&Ah[r * 72 + c8] = make_uint4(h0, h1, h2, h3);
                *(uint4*)&Al[r * 72 + c8] = make_uint4(l0, l1, l2, l3);
            }
            #pragma unroll
            for (int p = 0; p < 3; p++) {
                *(uint4*)&smg[(2+2*p)*GARR + r * 72 + c8] =
                    *(const uint4*)&Whi[(size_t)p * C_ * C_ + (size_t)(n0 + r) * C_ + k0 + c8];
                *(uint4*)&smg[(3+2*p)*GARR + r * 72 + c8] =
                    *(const uint4*)&Wlo[(size_t)p * C_ * C_ + (size_t)(n0 + r) * C_ + k0 + c8];
            }
        }
        __syncthreads();

        #pragma unroll
        for (int kt = 0; kt < 4; kt++) {
            uint32_t ah[4], al[4];
            ldmx4(ah, &Ah[(wr + (lane & 15)) * 72 + kt * 16 + (lane >> 4) * 8]);
            ldmx4(al, &Al[(wr + (lane & 15)) * 72 + kt * 16 + (lane >> 4) * 8]);
            #pragma unroll
            for (int p = 0; p < 3; p++) {
                const __nv_bfloat16* Bh = smg + (2+2*p)*GARR;
                const __nv_bfloat16* Bl = smg + (3+2*p)*GARR;
                #pragma unroll
                for (int jp = 0; jp < 4; jp++) {
                    uint32_t bh4[4], bl4[4];
                    ldmx4(bh4, Bh + (jp * 16 + k_rofs) * 72 + kt * 16 + k_cofs);
                    ldmx4(bl4, Bl + (jp * 16 + k_rofs) * 72 + kt * 16 + k_cofs);
                    mma_bf16(acc[p][2*jp],   ah[0], ah[1], ah[2], ah[3], bh4[0], bh4[1]);
                    mma_bf16(acc[p][2*jp+1], ah[0], ah[1], ah[2], ah[3], bh4[2], bh4[3]);
                    mma_bf16(acc[p][2*jp],   ah[0], ah[1], ah[2], ah[3], bl4[0], bl4[1]);
                    mma_bf16(acc[p][2*jp+1], ah[0], ah[1], ah[2], ah[3], bl4[2], bl4[3]);
                    mma_bf16(acc[p][2*jp],   al[0], al[1], al[2], al[3], bh4[0], bh4[1]);
                    mma_bf16(acc[p][2*jp+1], al[0], al[1], al[2], al[3], bh4[2], bh4[3]);
                }
            }
        }
    }

    const int g = lane >> 2, cc = (lane & 3) * 2;
    const int r0 = m0 + wr + g, r1 = r0 + 8;
    const int b0i = r0 >> 12, nl0 = r0 & 4095;
    const int b1i = r1 >> 12, nl1 = r1 & 4095;

    const float* biases[3] = {bq, bk, bv};
    __nv_bfloat16* ohis[3] = {qhi, khi, vhi};
    __nv_bfloat16* olos[3] = {qlo, klo, vlo};

    #pragma unroll
    for (int p = 0; p < 3; p++) {
        const float scale = (p == 0) ? QSCALE_ : 1.0f;
        #pragma unroll
        for (int jp = 0; jp < 4; jp++) {
            #pragma unroll
            for (int t = 0; t < 2; t++) {
                const int n = n0 + jp * 16 + t * 8 + cc;
                const float bb0 = __ldg(&biases[p][n]);
                const float bb1 = __ldg(&biases[p][n + 1]);
                float v00 = (acc[p][2*jp+t][0] + bb0) * scale;
                float v01 = (acc[p][2*jp+t][1] + bb1) * scale;
                float v10 = (acc[p][2*jp+t][2] + bb0) * scale;
                float v11 = (acc[p][2*jp+t][3] + bb1) * scale;
                const int h = n >> 6, d = n & 63;
                const size_t a0 = (((size_t)(b0i * H_ + h) * N_) + nl0) * D_ + d;
                const size_t a1 = (((size_t)(b1i * H_ + h) * N_) + nl1) * D_ + d;
                uint32_t h0, l0, h1, l1;
                split2(v00, v01, h0, l0);
                split2(v10, v11, h1, l1);
                *(uint32_t*)&ohis[p][a0] = h0;  *(uint32_t*)&olos[p][a0] = l0;
                *(uint32_t*)&ohis[p][a1] = h1;  *(uint32_t*)&olos[p][a1] = l1;
            }
        }
    }
}

// ---------------------------------------------------------------------------
// Out-projection GEMM (2-term; att exact bf16)
// ---------------------------------------------------------------------------
__global__ __launch_bounds__(128, 4)
void gemm_out(const __nv_bfloat16* __restrict__ Ahi,
              const __nv_bfloat16* __restrict__ Bhi, const __nv_bfloat16* __restrict__ Blo,
              const float* __restrict__ bias, float* __restrict__ ofp)
{
    __shared__ __align__(16) __nv_bfloat16 Ah[64][72];
    __shared__ __align__(16) __nv_bfloat16 Bh[64][72];
    __shared__ __align__(16) __nv_bfloat16 Bl[64][72];

    const int tid  = threadIdx.x;
    const int lane = tid & 31;
    const int wid  = tid >> 5;
    const int wr   = wid * 16;
    const int m0   = blockIdx.x * 64;
    const int n0   = blockIdx.y * 64;

    const int grp = lane >> 3, rr = lane & 7;
    const int k_rofs = ((grp & 2) ? 8 : 0) + rr;
    const int k_cofs = (grp & 1) ? 8 : 0;

    float s[8][4];
    #pragma unroll
    for (int i = 0; i < 8; i++) { s[i][0]=0.f; s[i][1]=0.f; s[i][2]=0.f; s[i][3]=0.f; }

    for (int kt0 = 0; kt0 < 4; kt0++) {
        const int k0 = kt0 * 64;
        __syncthreads();
        #pragma unroll
        for (int it = 0; it < 4; it++) {
            const int idx = it * 128 + tid;
            const int r = idx >> 3, c8 = (idx & 7) * 8;
            *(uint4*)&Ah[r][c8] = *(const uint4*)&Ahi[(size_t)(m0 + r) * C_ + k0 + c8];
            *(uint4*)&Bh[r][c8] = *(const uint4*)&Bhi[(size_t)(n0 + r) * C_ + k0 + c8];
            *(uint4*)&Bl[r][c8] = *(const uint4*)&Blo[(size_t)(n0 + r) * C_ + k0 + c8];
        }
        __syncthreads();

        #pragma unroll
        for (int kt = 0; kt < 4; kt++) {
            uint32_t ah[4];
            ldmx4(ah, &Ah[wr + (lane & 15)][kt * 16 + (lane >> 4) * 8]);
            #pragma unroll
            for (int jp = 0; jp < 4; jp++) {
                uint32_t bh4[4], bl4[4];
                ldmx4(bh4, &Bh[jp * 16 + k_rofs][kt * 16 + k_cofs]);
                ldmx4(bl4, &Bl[jp * 16 + k_rofs][kt * 16 + k_cofs]);
                mma_bf16(s[2*jp],   ah[0], ah[1], ah[2], ah[3], bh4[0], bh4[1]);
                mma_bf16(s[2*jp+1], ah[0], ah[1], ah[2], ah[3], bh4[2], bh4[3]);
                mma_bf16(s[2*jp],   ah[0], ah[1], ah[2], ah[3], bl4[0], bl4[1]);
                mma_bf16(s[2*jp+1], ah[0], ah[1], ah[2], ah[3], bl4[2], bl4[3]);
            }
        }
    }

    const int g = lane >> 2, cc = (lane & 3) * 2;
    const int r0 = m0 + wr + g, r1 = r0 + 8;
    #pragma unroll
    for (int jp = 0; jp < 4; jp++) {
        #pragma unroll
        for (int t = 0; t < 2; t++) {
            const int n = n0 + jp * 16 + t * 8 + cc;
            const float b0 = __ldg(&bias[n]);
            const float b1 = __ldg(&bias[n + 1]);
            *(float2*)&ofp[(size_t)r0 * C_ + n] = make_float2(s[2*jp+t][0] + b0, s[2*jp+t][1] + b1);
            *(float2*)&ofp[(size_t)r1 * C_ + n] = make_float2(s[2*jp+t][2] + b0, s[2*jp+t][3] + b1);
        }
    }
}

// ---------------------------------------------------------------------------
// Flash attention v9: 2 q-tiles/CTA (256 thr), triple-buffered K AND V rings
// -> ONE wait + ONE sync + ONE commit per tile (bottom staging targets the
// buffer freed at tile t-1, protected by the top sync of tile t).
// smem: K ring 3x16KB @0/16K/32K, V ring 3x16KB @48K/64K/80K = 96KB. 2 CTA/SM.
// ---------------------------------------------------------------------------
#define FKR   0u
#define FVR   49152u
#define SMEM_F 98304

__global__ __launch_bounds__(256, 2)
void flash9(const __nv_bfloat16* __restrict__ qhi, const __nv_bfloat16* __restrict__ qlo,
            const __nv_bfloat16* __restrict__ khi, const __nv_bfloat16* __restrict__ klo,
            const __nv_bfloat16* __restrict__ vhi, const __nv_bfloat16* __restrict__ vlo,
            __nv_bfloat16* __restrict__ att)
{
    extern __shared__ __align__(1024) char smf[];
    const uint32_t sb = (uint32_t)__cvta_generic_to_shared(smf);

    const int tid  = threadIdx.x;
    const int lane = tid & 31;
    const int wid  = tid >> 5;          // 0..7
    const int wr   = (wid & 3) * 16;    // warp row within its q-tile
    const int bh   = blockIdx.y;
    const int q0   = blockIdx.x * 128 + (wid >> 2) * 64;   // per-warp q-tile base

    const char* kh_g = (const char*)(khi + (size_t)bh * N_ * D_);
    const char* kl_g = (const char*)(klo + (size_t)bh * N_ * D_);
    const char* vh_g = (const char*)(vhi + (size_t)bh * N_ * D_);
    const char* vl_g = (const char*)(vlo + (size_t)bh * N_ * D_);

    // staging: 16KB (hi+lo pair) over 256 threads x 2 iters of 16B each
    #define STAGE_PAIR(dsth, dstl, srch, srcl, gofs)                               \
        {                                                                          \
            _Pragma("unroll")                                                      \
            for (int it = 0; it < 2; it++) {                                       \
                const int idx = it * 256 + tid;                                    \
                const int r = idx >> 3;                                            \
                const uint32_t c16 = (uint32_t)((idx & 7) * 16);                   \
                const uint32_t off = (uint32_t)(r * 128) + c16;                    \
                const uint32_t sw  = (uint32_t)(r * 128) + (c16 ^ (((uint32_t)r & 7) << 4)); \
                cpa16((dsth) + sw, (srch) + (gofs) + off);                         \
                cpa16((dstl) + sw, (srcl) + (gofs) + off);                         \
            }                                                                      \
        }

    // ---- prologue: G0 = {K0,V0}, G1 = {K1,V1} ----
    STAGE_PAIR(sb + FKR, sb + FKR + 8192, kh_g, kl_g, 0)
    STAGE_PAIR(sb + FVR, sb + FVR + 8192, vh_g, vl_g, 0)
    cpa_commit();
    STAGE_PAIR(sb + FKR + 16384, sb + FKR + 24576, kh_g, kl_g, 8192)
    STAGE_PAIR(sb + FVR + 16384, sb + FVR + 24576, vh_g, vl_g, 8192)
    cpa_commit();

    // Q fragments straight from gmem (Q pre-scaled by log2e/8, split)
    const int g  = lane >> 2;
    const int cc = (lane & 3) * 2;
    uint32_t qh[4][4], ql[4][4];
    {
        const size_t r0 = ((size_t)bh * N_ + q0 + wr + g) * D_;
        const size_t r1 = r0 + 8 * D_;
        #pragma unroll
        for (int kt = 0; kt < 4; kt++) {
            const int c = kt * 16 + cc;
            qh[kt][0] = *(const uint32_t*)&qhi[r0 + c];
            qh[kt][1] = *(const uint32_t*)&qhi[r1 + c];
            qh[kt][2] = *(const uint32_t*)&qhi[r0 + c + 8];
            qh[kt][3] = *(const uint32_t*)&qhi[r1 + c + 8];
            ql[kt][0] = *(const uint32_t*)&qlo[r0 + c];
            ql[kt][1] = *(const uint32_t*)&qlo[r1 + c];
            ql[kt][2] = *(const uint32_t*)&qlo[r0 + c + 8];
            ql[kt][3] = *(const uint32_t*)&qlo[r1 + c + 8];
        }
    }

    float o[8][4];
    #pragma unroll
    for (int i = 0; i < 8; i++) { o[i][0]=0.f; o[i][1]=0.f; o[i][2]=0.f; o[i][3]=0.f; }
    float l_g = 0.f, l_h = 0.f;

    // hoisted SW128 addressing: addr = base + R*128 + (col ^ (rr<<4))
    const int grp = lane >> 3, rr = lane & 7;
    const uint32_t xorv = (uint32_t)rr << 4;
    const uint32_t k_rowb = (uint32_t)((((grp & 2) ? 8 : 0) + rr) * 128);
    const uint32_t v_rowb = (uint32_t)((((grp & 1) ? 8 : 0) + rr) * 128);
    const uint32_t k_c2   = (grp & 1) ? 16u : 0u;
    const uint32_t v_c2   = (grp & 2) ? 16u : 0u;
    uint32_t colK[4], colV[4];
    #pragma unroll
    for (int i = 0; i < 4; i++) {
        colK[i] = ((uint32_t)(i * 32) + k_c2) ^ xorv;
        colV[i] = ((uint32_t)(i * 32) + v_c2) ^ xorv;
    }

    int cidx = 0;   // ring index of tile t (0,1,2,0,...)
    for (int kvt = 0; kvt < N_ / 64; kvt++) {
        cpa_wait<1>();     // G(kvt) complete (only G(kvt+1) may pend)
        __syncthreads();   // all warps past tile kvt-1; buffers (kvt+2)%3 free

        const uint32_t cofs = (uint32_t)cidx * 16384u;
        const uint32_t kb = sb + FKR + cofs + k_rowb;
        const uint32_t vb = sb + FVR + cofs + v_rowb;

        // ---- S = Q K^T (3-term) ----
        float s[8][4];
        #pragma unroll
        for (int i = 0; i < 8; i++) { s[i][0]=0.f; s[i][1]=0.f; s[i][2]=0.f; s[i][3]=0.f; }

        #pragma unroll
        for (int kt = 0; kt < 4; kt++) {
            #pragma unroll
            for (int jp = 0; jp < 4; jp++) {
                uint32_t bhr[4], blr[4];
                const uint32_t a = kb + (uint32_t)(jp * 2048) + colK[kt];
                ldmx4a(bhr, a);
                ldmx4a(blr, a + 8192);
                mma_bf16(s[2*jp],   qh[kt][0], qh[kt][1], qh[kt][2], qh[kt][3], bhr[0], bhr[1]);
                mma_bf16(s[2*jp+1], qh[kt][0], qh[kt][1], qh[kt][2], qh[kt][3], bhr[2], bhr[3]);
                mma_bf16(s[2*jp],   qh[kt][0], qh[kt][1], qh[kt][2], qh[kt][3], blr[0], blr[1]);
                mma_bf16(s[2*jp+1], qh[kt][0], qh[kt][1], qh[kt][2], qh[kt][3], blr[2], blr[3]);
                mma_bf16(s[2*jp],   ql[kt][0], ql[kt][1], ql[kt][2], ql[kt][3], bhr[0], bhr[1]);
                mma_bf16(s[2*jp+1], ql[kt][0], ql[kt][1], ql[kt][2], ql[kt][3], bhr[2], bhr[3]);
            }
        }

        // ---- max-free softmax: p = exp2(s') ----
        float sum_g = 0.f, sum_h = 0.f;
        #pragma unroll
        for (int nt = 0; nt < 8; nt++) {
            s[nt][0] = ex2(s[nt][0]);
            s[nt][1] = ex2(s[nt][1]);
            s[nt][2] = ex2(s[nt][2]);
            s[nt][3] = ex2(s[nt][3]);
            sum_g += s[nt][0] + s[nt][1];
            sum_h += s[nt][2] + s[nt][3];
        }
        l_g += sum_g;
        l_h += sum_h;

        // ---- O += P V (3-term, P frags in-register) ----
        #pragma unroll
        for (int kt = 0; kt < 4; kt++) {
            uint32_t pa0, pl0, pa1, pl1, pa2, pl2, pa3, pl3;
            split2(s[2*kt][0],   s[2*kt][1],   pa0, pl0);
            split2(s[2*kt][2],   s[2*kt][3],   pa1, pl1);
            split2(s[2*kt+1][0], s[2*kt+1][1], pa2, pl2);
            split2(s[2*kt+1][2], s[2*kt+1][3], pa3, pl3);

            #pragma unroll
            for (int dp = 0; dp < 4; dp++) {
                uint32_t vhr[4], vlr[4];
                const uint32_t a = vb + (uint32_t)(kt * 2048) + colV[dp];
                ldmx4ta(vhr, a);
                ldmx4ta(vlr, a + 8192);
                mma_bf16(o[2*dp],   pa0, pa1, pa2, pa3, vhr[0], vhr[1]);
                mma_bf16(o[2*dp+1], pa0, pa1, pa2, pa3, vhr[2], vhr[3]);
                mma_bf16(o[2*dp],   pa0, pa1, pa2, pa3, vlr[0], vlr[1]);
                mma_bf16(o[2*dp+1], pa0, pa1, pa2, pa3, vlr[2], vlr[3]);
                mma_bf16(o[2*dp],   pl0, pl1, pl2, pl3, vhr[0], vhr[1]);
                mma_bf16(o[2*dp+1], pl0, pl1, pl2, pl3, vhr[2], vhr[3]);
            }
        }

        // issue G(kvt+2) into ring slot (kvt+2)%3 (freed at tile kvt-1; all
        // warps passed this tile's top sync, so no bottom sync is needed)
        if (kvt + 2 < N_ / 64) {
            int nidx = cidx + 2; if (nidx >= 3) nidx -= 3;
            const uint32_t nofs = (uint32_t)nidx * 16384u;
            const size_t tb = (size_t)(kvt + 2) * 8192;
            STAGE_PAIR(sb + FKR + nofs, sb + FKR + nofs + 8192, kh_g, kl_g, tb)
            STAGE_PAIR(sb + FVR + nofs, sb + FVR + nofs + 8192, vh_g, vl_g, tb)
        }
        cpa_commit();
        cidx = (cidx == 2) ? 0 : cidx + 1;
    }

    // deferred l reduction (once)
    l_g += __shfl_xor_sync(0xffffffffu, l_g, 1);
    l_g += __shfl_xor_sync(0xffffffffu, l_g, 2);
    l_h += __shfl_xor_sync(0xffffffffu, l_h, 1);
    l_h += __shfl_xor_sync(0xffffffffu, l_h, 2);

    // ---- epilogue: normalize, write bf16 att ----
    const int b = bh >> 2;
    const int h = bh & 3;
    const float inv_g = 1.f / l_g;
    const float inv_h = 1.f / l_h;
    const int rg = q0 + wr + g;
    const int rh = rg + 8;

    #pragma unroll
    for (int dt = 0; dt < 8; dt++) {
        const int col = h * D_ + dt * 8 + cc;
        uint32_t wg = pack_bf2(o[dt][0] * inv_g, o[dt][1] * inv_g);
        uint32_t wh = pack_bf2(o[dt][2] * inv_h, o[dt][3] * inv_h);
        *(uint32_t*)&att[(size_t)(b * N_ + rg) * C_ + col] = wg;
        *(uint32_t*)&att[(size_t)(b * N_ + rh) * C_ + col] = wh;
    }
    #undef STAGE_PAIR
}

// ---------------------------------------------------------------------------
extern "C" void kernel_launch(void* const* d_in, const int* in_sizes, int n_in,
                              void* d_out, int out_size)
{
    (void)in_sizes; (void)n_in; (void)out_size;
    const float* x  = (const float*)d_in[0];
    const float* Wq = (const float*)d_in[1];
    const float* bq = (const float*)d_in[2];
    const float* Wk = (const float*)d_in[3];
    const float* bk = (const float*)d_in[4];
    const float* Wv = (const float*)d_in[5];
    const float* bv = (const float*)d_in[6];
    const float* Wo = (const float*)d_in[7];
    const float* bo = (const float*)d_in[8];
    float* out = (float*)d_out;

    __nv_bfloat16 *whi, *wlo, *qhi, *qlo, *khi, *klo, *vhi, *vlo, *att;
    cudaGetSymbolAddress((void**)&whi, g_whi);
    cudaGetSymbolAddress((void**)&wlo, g_wlo);
    cudaGetSymbolAddress((void**)&qhi, g_qhi);
    cudaGetSymbolAddress((void**)&qlo, g_qlo);
    cudaGetSymbolAddress((void**)&khi, g_khi);
    cudaGetSymbolAddress((void**)&klo, g_klo);
    cudaGetSymbolAddress((void**)&vhi, g_vhi);
    cudaGetSymbolAddress((void**)&vlo, g_vlo);
    cudaGetSymbolAddress((void**)&att, g_att);

    split_w4<<<dim3((C_*C_/4 + 255)/256, 4), 256>>>(Wq, Wk, Wv, Wo, whi, wlo);

    cudaFuncSetAttribute(gemm_qkv, cudaFuncAttributeMaxDynamicSharedMemorySize, 8*GARR*2);
    dim3 gGrid(MTOT / 64, C_ / 64);
    gemm_qkv<<<gGrid, 128, 8*GARR*2>>>(x, whi, wlo, bq, bk, bv,
                                       qhi, qlo, khi, klo, vhi, vlo);

    cudaFuncSetAttribute(flash9, cudaFuncAttributeMaxDynamicSharedMemorySize, SMEM_F);
    dim3 fGrid(N_ / 128, B_ * H_);
    flash9<<<fGrid, 256, SMEM_F>>>(qhi, qlo, khi, klo, vhi, vlo, att);

    gemm_out<<<gGrid, 128>>>(att, whi + 3*C_*C_, wlo + 3*C_*C_, bo, out);
}

// round 13
// speedup vs baseline: 1.0815x; 1.0815x over previous
#include <cuda_runtime.h>
#include <cuda_bf16.h>
#include <math.h>
#include <stdint.h>

#define B_      2
#define N_      4096
#define C_      256
#define H_      4
#define D_      64
#define MTOT    (B_*N_)        // 8192
// Q pre-scale: (1/8) * log2(e)  -> softmax numerator = exp2(S')
#define QSCALE_ 0.18033688011112042f
#define NSLICE  4
#define TILES_PER_SLICE 16

// Scratch (device globals; allocation-free)
__device__ __nv_bfloat16 g_whi[4][C_*C_], g_wlo[4][C_*C_];
__device__ __nv_bfloat16 g_qhi[MTOT*C_], g_qlo[MTOT*C_];   // [bh][n][d], Q pre-scaled
__device__ __nv_bfloat16 g_khi[MTOT*C_], g_klo[MTOT*C_];   // [bh][n][d]
__device__ __nv_bfloat16 g_vhi[MTOT*C_], g_vlo[MTOT*C_];   // [bh][n][d]
__device__ __nv_bfloat16 g_att[MTOT*C_];                   // [B*N][C] bf16 (exact)
__device__ float g_opart[512*NSLICE*64*64];                // unnormalized O partials
__device__ float g_lpart[512*NSLICE*64];                   // l partials

// ---------------------------------------------------------------------------
// helpers
// ---------------------------------------------------------------------------
__device__ __forceinline__ void mma_bf16(float c[4],
    uint32_t a0, uint32_t a1, uint32_t a2, uint32_t a3,
    uint32_t b0, uint32_t b1)
{
    asm volatile(
        "mma.sync.aligned.m16n8k16.row.col.f32.bf16.bf16.f32 "
        "{%0,%1,%2,%3}, {%4,%5,%6,%7}, {%8,%9}, {%0,%1,%2,%3};"
        : "+f"(c[0]), "+f"(c[1]), "+f"(c[2]), "+f"(c[3])
        : "r"(a0), "r"(a1), "r"(a2), "r"(a3), "r"(b0), "r"(b1));
}
__device__ __forceinline__ void ldmx4(uint32_t r[4], const void* p)
{
    uint32_t a = (uint32_t)__cvta_generic_to_shared(p);
    asm volatile("ldmatrix.sync.aligned.m8n8.x4.shared.b16 {%0,%1,%2,%3}, [%4];"
                 : "=r"(r[0]), "=r"(r[1]), "=r"(r[2]), "=r"(r[3]) : "r"(a));
}
__device__ __forceinline__ void ldmx4a(uint32_t r[4], uint32_t a)
{
    asm volatile("ldmatrix.sync.aligned.m8n8.x4.shared.b16 {%0,%1,%2,%3}, [%4];"
                 : "=r"(r[0]), "=r"(r[1]), "=r"(r[2]), "=r"(r[3]) : "r"(a));
}
__device__ __forceinline__ void ldmx4ta(uint32_t r[4], uint32_t a)
{
    asm volatile("ldmatrix.sync.aligned.m8n8.x4.trans.shared.b16 {%0,%1,%2,%3}, [%4];"
                 : "=r"(r[0]), "=r"(r[1]), "=r"(r[2]), "=r"(r[3]) : "r"(a));
}
__device__ __forceinline__ uint32_t pack_bf2(float a, float b)
{
    __nv_bfloat162 t = __floats2bfloat162_rn(a, b);
    return *(uint32_t*)&t;
}
__device__ __forceinline__ void cpa16(uint32_t dst, const void* src)
{
    asm volatile("cp.async.cg.shared.global [%0], [%1], 16;" :: "r"(dst), "l"(src));
}
__device__ __forceinline__ void cpa_commit()
{
    asm volatile("cp.async.commit_group;" ::: "memory");
}
template<int N>
__device__ __forceinline__ void cpa_wait()
{
    asm volatile("cp.async.wait_group %0;" :: "n"(N) : "memory");
}
__device__ __forceinline__ void split2(float a, float b, uint32_t& hi, uint32_t& lo)
{
    hi = pack_bf2(a, b);
    __nv_bfloat162 t = *(__nv_bfloat162*)&hi;
    float2 f = __bfloat1622float2(t);
    lo = pack_bf2(a - f.x, b - f.y);
}
__device__ __forceinline__ float ex2(float x)
{
    float r;
    asm("ex2.approx.f32 %0, %1;" : "=f"(r) : "f"(x));
    return r;
}

// ---------------------------------------------------------------------------
// split weights fp32 -> bf16 hi/lo (all 4 in one launch)
// ---------------------------------------------------------------------------
__global__ void split_w4(const float* __restrict__ w0, const float* __restrict__ w1,
                         const float* __restrict__ w2, const float* __restrict__ w3,
                         __nv_bfloat16* __restrict__ hi, __nv_bfloat16* __restrict__ lo)
{
    const int p = blockIdx.y;
    const float* src = (p == 0) ? w0 : (p == 1) ? w1 : (p == 2) ? w2 : w3;
    int i = blockIdx.x * blockDim.x + threadIdx.x;
    if (i >= C_*C_/4) return;
    float4 v = ((const float4*)src)[i];
    uint32_t h01, l01, h23, l23;
    split2(v.x, v.y, h01, l01);
    split2(v.z, v.w, h23, l23);
    ((uint2*)(hi + (size_t)p * C_ * C_))[i] = make_uint2(h01, h23);
    ((uint2*)(lo + (size_t)p * C_ * C_))[i] = make_uint2(l01, l23);
}

// ---------------------------------------------------------------------------
// Fused Q/K/V projection (3-term split bf16 MMA), NT. x clip+split inline.
// ---------------------------------------------------------------------------
#define GARR 4608   // elements per [64][72] array

__global__ __launch_bounds__(128, 3)
void gemm_qkv(const float* __restrict__ x,
              const __nv_bfloat16* __restrict__ Whi, const __nv_bfloat16* __restrict__ Wlo,
              const float* __restrict__ bq, const float* __restrict__ bk,
              const float* __restrict__ bv,
              __nv_bfloat16* __restrict__ qhi, __nv_bfloat16* __restrict__ qlo,
              __nv_bfloat16* __restrict__ khi, __nv_bfloat16* __restrict__ klo,
              __nv_bfloat16* __restrict__ vhi, __nv_bfloat16* __restrict__ vlo)
{
    extern __shared__ __align__(16) __nv_bfloat16 smg[];
    __nv_bfloat16* Ah = smg;
    __nv_bfloat16* Al = smg + GARR;

    const int tid  = threadIdx.x;
    const int lane = tid & 31;
    const int wid  = tid >> 5;
    const int wr   = wid * 16;
    const int m0   = blockIdx.x * 64;
    const int n0   = blockIdx.y * 64;

    const int grp = lane >> 3, rr = lane & 7;
    const int k_rofs = ((grp & 2) ? 8 : 0) + rr;
    const int k_cofs = (grp & 1) ? 8 : 0;

    float acc[3][8][4];
    #pragma unroll
    for (int p = 0; p < 3; p++)
        #pragma unroll
        for (int i = 0; i < 8; i++)
            { acc[p][i][0]=0.f; acc[p][i][1]=0.f; acc[p][i][2]=0.f; acc[p][i][3]=0.f; }

    for (int kt0 = 0; kt0 < 4; kt0++) {
        const int k0 = kt0 * 64;
        __syncthreads();
        #pragma unroll
        for (int it = 0; it < 4; it++) {
            const int idx = it * 128 + tid;
            const int r = idx >> 3, c8 = (idx & 7) * 8;
            {
                const float* xp = &x[(size_t)(m0 + r) * C_ + k0 + c8];
                float4 v0 = *(const float4*)xp;
                float4 v1 = *(const float4*)(xp + 4);
                v0.x = fminf(fmaxf(v0.x, -10000.f), 10000.f);
                v0.y = fminf(fmaxf(v0.y, -10000.f), 10000.f);
                v0.z = fminf(fmaxf(v0.z, -10000.f), 10000.f);
                v0.w = fminf(fmaxf(v0.w, -10000.f), 10000.f);
                v1.x = fminf(fmaxf(v1.x, -10000.f), 10000.f);
                v1.y = fminf(fmaxf(v1.y, -10000.f), 10000.f);
                v1.z = fminf(fmaxf(v1.z, -10000.f), 10000.f);
                v1.w = fminf(fmaxf(v1.w, -10000.f), 10000.f);
                uint32_t h0, l0, h1, l1, h2, l2, h3, l3;
                split2(v0.x, v0.y, h0, l0);
                split2(v0.z, v0.w, h1, l1);
                split2(v1.x, v1.y, h2, l2);
                split2(v1.z, v1.w, h3, l3);
                *(uint4*)&Ah[r * 72 + c8] = make_uint4(h0, h1, h2, h3);
                *(uint4*)&Al[r * 72 + c8] = make_uint4(l0, l1, l2, l3);
            }
            #pragma unroll
            for (int p = 0; p < 3; p++) {
                *(uint4*)&smg[(2+2*p)*GARR + r * 72 + c8] =
                    *(const uint4*)&Whi[(size_t)p * C_ * C_ + (size_t)(n0 + r) * C_ + k0 + c8];
                *(uint4*)&smg[(3+2*p)*GARR + r * 72 + c8] =
                    *(const uint4*)&Wlo[(size_t)p * C_ * C_ + (size_t)(n0 + r) * C_ + k0 + c8];
            }
        }
        __syncthreads();

        #pragma unroll
        for (int kt = 0; kt < 4; kt++) {
            uint32_t ah[4], al[4];
            ldmx4(ah, &Ah[(wr + (lane & 15)) * 72 + kt * 16 + (lane >> 4) * 8]);
            ldmx4(al, &Al[(wr + (lane & 15)) * 72 + kt * 16 + (lane >> 4) * 8]);
            #pragma unroll
            for (int p = 0; p < 3; p++) {
                const __nv_bfloat16* Bh = smg + (2+2*p)*GARR;
                const __nv_bfloat16* Bl = smg + (3+2*p)*GARR;
                #pragma unroll
                for (int jp = 0; jp < 4; jp++) {
                    uint32_t bh4[4], bl4[4];
                    ldmx4(bh4, Bh + (jp * 16 + k_rofs) * 72 + kt * 16 + k_cofs);
                    ldmx4(bl4, Bl + (jp * 16 + k_rofs) * 72 + kt * 16 + k_cofs);
                    mma_bf16(acc[p][2*jp],   ah[0], ah[1], ah[2], ah[3], bh4[0], bh4[1]);
                    mma_bf16(acc[p][2*jp+1], ah[0], ah[1], ah[2], ah[3], bh4[2], bh4[3]);
                    mma_bf16(acc[p][2*jp],   ah[0], ah[1], ah[2], ah[3], bl4[0], bl4[1]);
                    mma_bf16(acc[p][2*jp+1], ah[0], ah[1], ah[2], ah[3], bl4[2], bl4[3]);
                    mma_bf16(acc[p][2*jp],   al[0], al[1], al[2], al[3], bh4[0], bh4[1]);
                    mma_bf16(acc[p][2*jp+1], al[0], al[1], al[2], al[3], bh4[2], bh4[3]);
                }
            }
        }
    }

    const int g = lane >> 2, cc = (lane & 3) * 2;
    const int r0 = m0 + wr + g, r1 = r0 + 8;
    const int b0i = r0 >> 12, nl0 = r0 & 4095;
    const int b1i = r1 >> 12, nl1 = r1 & 4095;

    const float* biases[3] = {bq, bk, bv};
    __nv_bfloat16* ohis[3] = {qhi, khi, vhi};
    __nv_bfloat16* olos[3] = {qlo, klo, vlo};

    #pragma unroll
    for (int p = 0; p < 3; p++) {
        const float scale = (p == 0) ? QSCALE_ : 1.0f;
        #pragma unroll
        for (int jp = 0; jp < 4; jp++) {
            #pragma unroll
            for (int t = 0; t < 2; t++) {
                const int n = n0 + jp * 16 + t * 8 + cc;
                const float bb0 = __ldg(&biases[p][n]);
                const float bb1 = __ldg(&biases[p][n + 1]);
                float v00 = (acc[p][2*jp+t][0] + bb0) * scale;
                float v01 = (acc[p][2*jp+t][1] + bb1) * scale;
                float v10 = (acc[p][2*jp+t][2] + bb0) * scale;
                float v11 = (acc[p][2*jp+t][3] + bb1) * scale;
                const int h = n >> 6, d = n & 63;
                const size_t a0 = (((size_t)(b0i * H_ + h) * N_) + nl0) * D_ + d;
                const size_t a1 = (((size_t)(b1i * H_ + h) * N_) + nl1) * D_ + d;
                uint32_t h0, l0, h1, l1;
                split2(v00, v01, h0, l0);
                split2(v10, v11, h1, l1);
                *(uint32_t*)&ohis[p][a0] = h0;  *(uint32_t*)&olos[p][a0] = l0;
                *(uint32_t*)&ohis[p][a1] = h1;  *(uint32_t*)&olos[p][a1] = l1;
            }
        }
    }
}

// ---------------------------------------------------------------------------
// Out-projection GEMM (2-term; att exact bf16)
// ---------------------------------------------------------------------------
__global__ __launch_bounds__(128, 4)
void gemm_out(const __nv_bfloat16* __restrict__ Ahi,
              const __nv_bfloat16* __restrict__ Bhi, const __nv_bfloat16* __restrict__ Blo,
              const float* __restrict__ bias, float* __restrict__ ofp)
{
    __shared__ __align__(16) __nv_bfloat16 Ah[64][72];
    __shared__ __align__(16) __nv_bfloat16 Bh[64][72];
    __shared__ __align__(16) __nv_bfloat16 Bl[64][72];

    const int tid  = threadIdx.x;
    const int lane = tid & 31;
    const int wid  = tid >> 5;
    const int wr   = wid * 16;
    const int m0   = blockIdx.x * 64;
    const int n0   = blockIdx.y * 64;

    const int grp = lane >> 3, rr = lane & 7;
    const int k_rofs = ((grp & 2) ? 8 : 0) + rr;
    const int k_cofs = (grp & 1) ? 8 : 0;

    float s[8][4];
    #pragma unroll
    for (int i = 0; i < 8; i++) { s[i][0]=0.f; s[i][1]=0.f; s[i][2]=0.f; s[i][3]=0.f; }

    for (int kt0 = 0; kt0 < 4; kt0++) {
        const int k0 = kt0 * 64;
        __syncthreads();
        #pragma unroll
        for (int it = 0; it < 4; it++) {
            const int idx = it * 128 + tid;
            const int r = idx >> 3, c8 = (idx & 7) * 8;
            *(uint4*)&Ah[r][c8] = *(const uint4*)&Ahi[(size_t)(m0 + r) * C_ + k0 + c8];
            *(uint4*)&Bh[r][c8] = *(const uint4*)&Bhi[(size_t)(n0 + r) * C_ + k0 + c8];
            *(uint4*)&Bl[r][c8] = *(const uint4*)&Blo[(size_t)(n0 + r) * C_ + k0 + c8];
        }
        __syncthreads();

        #pragma unroll
        for (int kt = 0; kt < 4; kt++) {
            uint32_t ah[4];
            ldmx4(ah, &Ah[wr + (lane & 15)][kt * 16 + (lane >> 4) * 8]);
            #pragma unroll
            for (int jp = 0; jp < 4; jp++) {
                uint32_t bh4[4], bl4[4];
                ldmx4(bh4, &Bh[jp * 16 + k_rofs][kt * 16 + k_cofs]);
                ldmx4(bl4, &Bl[jp * 16 + k_rofs][kt * 16 + k_cofs]);
                mma_bf16(s[2*jp],   ah[0], ah[1], ah[2], ah[3], bh4[0], bh4[1]);
                mma_bf16(s[2*jp+1], ah[0], ah[1], ah[2], ah[3], bh4[2], bh4[3]);
                mma_bf16(s[2*jp],   ah[0], ah[1], ah[2], ah[3], bl4[0], bl4[1]);
                mma_bf16(s[2*jp+1], ah[0], ah[1], ah[2], ah[3], bl4[2], bl4[3]);
            }
        }
    }

    const int g = lane >> 2, cc = (lane & 3) * 2;
    const int r0 = m0 + wr + g, r1 = r0 + 8;
    #pragma unroll
    for (int jp = 0; jp < 4; jp++) {
        #pragma unroll
        for (int t = 0; t < 2; t++) {
            const int n = n0 + jp * 16 + t * 8 + cc;
            const float b0 = __ldg(&bias[n]);
            const float b1 = __ldg(&bias[n + 1]);
            *(float2*)&ofp[(size_t)r0 * C_ + n] = make_float2(s[2*jp+t][0] + b0, s[2*jp+t][1] + b1);
            *(float2*)&ofp[(size_t)r1 * C_ + n] = make_float2(s[2*jp+t][2] + b0, s[2*jp+t][3] + b1);
        }
    }
}

// ---------------------------------------------------------------------------
// Flash attention v10: flash5 inner loop verbatim, split-KV by 4 slices of
// 16 tiles (max-free softmax => partials are purely additive). grid.z=slice.
// Writes unnormalized O (f32) + l partials; merge kernel combines.
// smem: K0h@0 K0l@8K K1h@16K K1l@24K Vh@32K Vl@40K = 48KB. 4 CTAs/SM.
// 2048 CTAs -> 13.8/SM avg, max 14 (1.4% imbalance vs 15.6% before).
// ---------------------------------------------------------------------------
#define FK0   0u
#define FK1   16384u
#define FV    32768u
#define SMEM_F 49152

__global__ __launch_bounds__(128, 4)
void flash10(const __nv_bfloat16* __restrict__ qhi, const __nv_bfloat16* __restrict__ qlo,
             const __nv_bfloat16* __restrict__ khi, const __nv_bfloat16* __restrict__ klo,
             const __nv_bfloat16* __restrict__ vhi, const __nv_bfloat16* __restrict__ vlo,
             float* __restrict__ opart, float* __restrict__ lpart)
{
    extern __shared__ __align__(1024) char smf[];
    const uint32_t sb = (uint32_t)__cvta_generic_to_shared(smf);

    const int tid  = threadIdx.x;
    const int lane = tid & 31;
    const int wid  = tid >> 5;
    const int wr   = wid * 16;
    const int bh   = blockIdx.y;
    const int q0   = blockIdx.x * 64;
    const int slice = blockIdx.z;
    const int kt_beg = slice * TILES_PER_SLICE;
    const int kt_end = kt_beg + TILES_PER_SLICE;

    const char* kh_g = (const char*)(khi + (size_t)bh * N_ * D_);
    const char* kl_g = (const char*)(klo + (size_t)bh * N_ * D_);
    const char* vh_g = (const char*)(vhi + (size_t)bh * N_ * D_);
    const char* vl_g = (const char*)(vlo + (size_t)bh * N_ * D_);

    // staging geometry (algebraic SW128)
    const int st_r   = tid >> 3;
    const int st_c16 = (tid & 7) * 16;
    const uint32_t st_sc = (uint32_t)st_c16 ^ (((uint32_t)st_r & 7) << 4);

    // ---- prologue: groups {K(beg)}, {V(beg)}, {K(beg+1)} ----
    {
        const size_t tb0 = (size_t)kt_beg * 8192;
        #pragma unroll
        for (int it = 0; it < 4; it++) {
            const uint32_t off = (uint32_t)((st_r + it * 16) * 128 + st_c16);
            const uint32_t sw  = (uint32_t)((st_r + it * 16) * 128) + st_sc;
            cpa16(sb + FK0 + sw,        kh_g + tb0 + off);
            cpa16(sb + FK0 + 8192 + sw, kl_g + tb0 + off);
        }
        cpa_commit();
        #pragma unroll
        for (int it = 0; it < 4; it++) {
            const uint32_t off = (uint32_t)((st_r + it * 16) * 128 + st_c16);
            const uint32_t sw  = (uint32_t)((st_r + it * 16) * 128) + st_sc;
            cpa16(sb + FV + sw,        vh_g + tb0 + off);
            cpa16(sb + FV + 8192 + sw, vl_g + tb0 + off);
        }
        cpa_commit();
        #pragma unroll
        for (int it = 0; it < 4; it++) {
            const uint32_t off = (uint32_t)((st_r + it * 16) * 128 + st_c16);
            const uint32_t sw  = (uint32_t)((st_r + it * 16) * 128) + st_sc;
            cpa16(sb + FK1 + sw,        kh_g + tb0 + 8192 + off);
            cpa16(sb + FK1 + 8192 + sw, kl_g + tb0 + 8192 + off);
        }
        cpa_commit();
    }

    // Q fragments straight from gmem (Q pre-scaled by log2e/8, split)
    const int g  = lane >> 2;
    const int cc = (lane & 3) * 2;
    uint32_t qh[4][4], ql[4][4];
    {
        const size_t r0 = ((size_t)bh * N_ + q0 + wr + g) * D_;
        const size_t r1 = r0 + 8 * D_;
        #pragma unroll
        for (int kt = 0; kt < 4; kt++) {
            const int c = kt * 16 + cc;
            qh[kt][0] = *(const uint32_t*)&qhi[r0 + c];
            qh[kt][1] = *(const uint32_t*)&qhi[r1 + c];
            qh[kt][2] = *(const uint32_t*)&qhi[r0 + c + 8];
            qh[kt][3] = *(const uint32_t*)&qhi[r1 + c + 8];
            ql[kt][0] = *(const uint32_t*)&qlo[r0 + c];
            ql[kt][1] = *(const uint32_t*)&qlo[r1 + c];
            ql[kt][2] = *(const uint32_t*)&qlo[r0 + c + 8];
            ql[kt][3] = *(const uint32_t*)&qlo[r1 + c + 8];
        }
    }

    float o[8][4];
    #pragma unroll
    for (int i = 0; i < 8; i++) { o[i][0]=0.f; o[i][1]=0.f; o[i][2]=0.f; o[i][3]=0.f; }
    float l_g = 0.f, l_h = 0.f;

    // hoisted SW128 addressing: addr = base + R*128 + (col ^ (rr<<4))
    const int grp = lane >> 3, rr = lane & 7;
    const uint32_t xorv = (uint32_t)rr << 4;
    const uint32_t k_rowb = (uint32_t)((((grp & 2) ? 8 : 0) + rr) * 128);
    const uint32_t v_rowb = (uint32_t)((((grp & 1) ? 8 : 0) + rr) * 128);
    const uint32_t k_c2   = (grp & 1) ? 16u : 0u;
    const uint32_t v_c2   = (grp & 2) ? 16u : 0u;
    uint32_t colK[4], colV[4];
    #pragma unroll
    for (int i = 0; i < 4; i++) {
        colK[i] = ((uint32_t)(i * 32) + k_c2) ^ xorv;
        colV[i] = ((uint32_t)(i * 32) + v_c2) ^ xorv;
    }

    for (int kvt = kt_beg; kvt < kt_end; kvt++) {
        cpa_wait<1>();     // K(kvt) (2-tile lead) and V(kvt) (1-tile lead) ready
        __syncthreads();

        const uint32_t kb = sb + ((kvt & 1) ? FK1 : FK0) + k_rowb;
        const uint32_t vb = sb + FV + v_rowb;

        // ---- S = Q K^T (3-term) ----
        float s[8][4];
        #pragma unroll
        for (int i = 0; i < 8; i++) { s[i][0]=0.f; s[i][1]=0.f; s[i][2]=0.f; s[i][3]=0.f; }

        #pragma unroll
        for (int kt = 0; kt < 4; kt++) {
            #pragma unroll
            for (int jp = 0; jp < 4; jp++) {
                uint32_t bhr[4], blr[4];
                const uint32_t a = kb + (uint32_t)(jp * 2048) + colK[kt];
                ldmx4a(bhr, a);
                ldmx4a(blr, a + 8192);
                mma_bf16(s[2*jp],   qh[kt][0], qh[kt][1], qh[kt][2], qh[kt][3], bhr[0], bhr[1]);
                mma_bf16(s[2*jp+1], qh[kt][0], qh[kt][1], qh[kt][2], qh[kt][3], bhr[2], bhr[3]);
                mma_bf16(s[2*jp],   qh[kt][0], qh[kt][1], qh[kt][2], qh[kt][3], blr[0], blr[1]);
                mma_bf16(s[2*jp+1], qh[kt][0], qh[kt][1], qh[kt][2], qh[kt][3], blr[2], blr[3]);
                mma_bf16(s[2*jp],   ql[kt][0], ql[kt][1], ql[kt][2], ql[kt][3], bhr[0], bhr[1]);
                mma_bf16(s[2*jp+1], ql[kt][0], ql[kt][1], ql[kt][2], ql[kt][3], bhr[2], bhr[3]);
            }
        }

        // ---- max-free softmax: p = exp2(s') ----
        float sum_g = 0.f, sum_h = 0.f;
        #pragma unroll
        for (int nt = 0; nt < 8; nt++) {
            s[nt][0] = ex2(s[nt][0]);
            s[nt][1] = ex2(s[nt][1]);
            s[nt][2] = ex2(s[nt][2]);
            s[nt][3] = ex2(s[nt][3]);
            sum_g += s[nt][0] + s[nt][1];
            sum_h += s[nt][2] + s[nt][3];
        }
        l_g += sum_g;
        l_h += sum_h;

        // ---- O += P V (3-term, P frags in-register) ----
        #pragma unroll
        for (int kt = 0; kt < 4; kt++) {
            uint32_t pa0, pl0, pa1, pl1, pa2, pl2, pa3, pl3;
            split2(s[2*kt][0],   s[2*kt][1],   pa0, pl0);
            split2(s[2*kt][2],   s[2*kt][3],   pa1, pl1);
            split2(s[2*kt+1][0], s[2*kt+1][1], pa2, pl2);
            split2(s[2*kt+1][2], s[2*kt+1][3], pa3, pl3);

            #pragma unroll
            for (int dp = 0; dp < 4; dp++) {
                uint32_t vhr[4], vlr[4];
                const uint32_t a = vb + (uint32_t)(kt * 2048) + colV[dp];
                ldmx4ta(vhr, a);
                ldmx4ta(vlr, a + 8192);
                mma_bf16(o[2*dp],   pa0, pa1, pa2, pa3, vhr[0], vhr[1]);
                mma_bf16(o[2*dp+1], pa0, pa1, pa2, pa3, vhr[2], vhr[3]);
                mma_bf16(o[2*dp],   pa0, pa1, pa2, pa3, vlr[0], vlr[1]);
                mma_bf16(o[2*dp+1], pa0, pa1, pa2, pa3, vlr[2], vlr[3]);
                mma_bf16(o[2*dp],   pl0, pl1, pl2, pl3, vhr[0], vhr[1]);
                mma_bf16(o[2*dp+1], pl0, pl1, pl2, pl3, vhr[2], vhr[3]);
            }
        }

        __syncthreads();   // all warps done reading V(kvt) and K(kvt) buffers

        // issue group{V(kvt+1)} then group{K(kvt+2)} (empty groups keep count)
        if (kvt + 1 < kt_end) {
            const size_t tb = (size_t)(kvt + 1) * 8192;
            #pragma unroll
            for (int it = 0; it < 4; it++) {
                const uint32_t off = (uint32_t)((st_r + it * 16) * 128 + st_c16);
                const uint32_t sw  = (uint32_t)((st_r + it * 16) * 128) + st_sc;
                cpa16(sb + FV + sw,        vh_g + tb + off);
                cpa16(sb + FV + 8192 + sw, vl_g + tb + off);
            }
        }
        cpa_commit();
        if (kvt + 2 < kt_end) {
            const uint32_t kb2 = sb + ((kvt & 1) ? FK1 : FK0);
            const size_t tb = (size_t)(kvt + 2) * 8192;
            #pragma unroll
            for (int it = 0; it < 4; it++) {
                const uint32_t off = (uint32_t)((st_r + it * 16) * 128 + st_c16);
                const uint32_t sw  = (uint32_t)((st_r + it * 16) * 128) + st_sc;
                cpa16(kb2 + sw,        kh_g + tb + off);
                cpa16(kb2 + 8192 + sw, kl_g + tb + off);
            }
        }
        cpa_commit();
    }

    // l reduction (once)
    l_g += __shfl_xor_sync(0xffffffffu, l_g, 1);
    l_g += __shfl_xor_sync(0xffffffffu, l_g, 2);
    l_h += __shfl_xor_sync(0xffffffffu, l_h, 1);
    l_h += __shfl_xor_sync(0xffffffffu, l_h, 2);

    // ---- epilogue: write unnormalized f32 partial + l ----
    const int qindex = bh * 64 + blockIdx.x;                 // 0..511
    float* op = opart + ((size_t)(qindex * NSLICE + slice)) * 4096;
    float* lp = lpart + ((size_t)(qindex * NSLICE + slice)) * 64;
    const int rg = wr + g;        // local row 0..63
    const int rh = rg + 8;

    #pragma unroll
    for (int dt = 0; dt < 8; dt++) {
        const int col = dt * 8 + cc;
        *(float2*)&op[rg * 64 + col] = make_float2(o[dt][0], o[dt][1]);
        *(float2*)&op[rh * 64 + col] = make_float2(o[dt][2], o[dt][3]);
    }
    if ((lane & 3) == 0) {
        lp[rg] = l_g;
        lp[rh] = l_h;
    }
}

// ---------------------------------------------------------------------------
// Merge: att[row, col] = bf16( (sum_s O_s) / (sum_s l_s) )
// grid 512 (qindex), block 256: thread = (row = tid>>2, 16 cols).
// ---------------------------------------------------------------------------
__global__ __launch_bounds__(256)
void merge_att(const float* __restrict__ opart, const float* __restrict__ lpart,
               __nv_bfloat16* __restrict__ att)
{
    const int qindex = blockIdx.x;
    const int bh = qindex >> 6, qt = qindex & 63;
    const int b = bh >> 2, h = bh & 3;
    const int tid = threadIdx.x;
    const int r  = tid >> 2;
    const int cb = (tid & 3) * 16;

    const float* op = opart + (size_t)(qindex * NSLICE) * 4096;
    const float* lp = lpart + (size_t)(qindex * NSLICE) * 64;

    float l = lp[r] + lp[64 + r] + lp[128 + r] + lp[192 + r];
    const float inv = 1.f / l;

    uint32_t w[8];
    #pragma unroll
    for (int c4 = 0; c4 < 4; c4++) {
        const int ofs = r * 64 + cb + c4 * 4;
        float4 a0 = *(const float4*)&op[ofs];
        float4 a1 = *(const float4*)&op[4096 + ofs];
        float4 a2 = *(const float4*)&op[8192 + ofs];
        float4 a3 = *(const float4*)&op[12288 + ofs];
        float x0 = (a0.x + a1.x + a2.x + a3.x) * inv;
        float x1 = (a0.y + a1.y + a2.y + a3.y) * inv;
        float x2 = (a0.z + a1.z + a2.z + a3.z) * inv;
        float x3 = (a0.w + a1.w + a2.w + a3.w) * inv;
        w[c4*2]   = pack_bf2(x0, x1);
        w[c4*2+1] = pack_bf2(x2, x3);
    }
    __nv_bfloat16* dst = att + (size_t)(b * N_ + qt * 64 + r) * C_ + h * D_ + cb;
    *(uint4*)dst       = make_uint4(w[0], w[1], w[2], w[3]);
    *(uint4*)(dst + 8) = make_uint4(w[4], w[5], w[6], w[7]);
}

// ---------------------------------------------------------------------------
extern "C" void kernel_launch(void* const* d_in, const int* in_sizes, int n_in,
                              void* d_out, int out_size)
{
    (void)in_sizes; (void)n_in; (void)out_size;
    const float* x  = (const float*)d_in[0];
    const float* Wq = (const float*)d_in[1];
    const float* bq = (const float*)d_in[2];
    const float* Wk = (const float*)d_in[3];
    const float* bk = (const float*)d_in[4];
    const float* Wv = (const float*)d_in[5];
    const float* bv = (const float*)d_in[6];
    const float* Wo = (const float*)d_in[7];
    const float* bo = (const float*)d_in[8];
    float* out = (float*)d_out;

    __nv_bfloat16 *whi, *wlo, *qhi, *qlo, *khi, *klo, *vhi, *vlo, *att;
    float *opart, *lpart;
    cudaGetSymbolAddress((void**)&whi, g_whi);
    cudaGetSymbolAddress((void**)&wlo, g_wlo);
    cudaGetSymbolAddress((void**)&qhi, g_qhi);
    cudaGetSymbolAddress((void**)&qlo, g_qlo);
    cudaGetSymbolAddress((void**)&khi, g_khi);
    cudaGetSymbolAddress((void**)&klo, g_klo);
    cudaGetSymbolAddress((void**)&vhi, g_vhi);
    cudaGetSymbolAddress((void**)&vlo, g_vlo);
    cudaGetSymbolAddress((void**)&att, g_att);
    cudaGetSymbolAddress((void**)&opart, g_opart);
    cudaGetSymbolAddress((void**)&lpart, g_lpart);

    split_w4<<<dim3((C_*C_/4 + 255)/256, 4), 256>>>(Wq, Wk, Wv, Wo, whi, wlo);

    cudaFuncSetAttribute(gemm_qkv, cudaFuncAttributeMaxDynamicSharedMemorySize, 8*GARR*2);
    dim3 gGrid(MTOT / 64, C_ / 64);
    gemm_qkv<<<gGrid, 128, 8*GARR*2>>>(x, whi, wlo, bq, bk, bv,
                                       qhi, qlo, khi, klo, vhi, vlo);

    cudaFuncSetAttribute(flash10, cudaFuncAttributeMaxDynamicSharedMemorySize, SMEM_F);
    dim3 fGrid(N_ / 64, B_ * H_, NSLICE);
    flash10<<<fGrid, 128, SMEM_F>>>(qhi, qlo, khi, klo, vhi, vlo, opart, lpart);

    merge_att<<<512, 256>>>(opart, lpart, att);

    gemm_out<<<gGrid, 128>>>(att, whi + 3*C_*C_, wlo + 3*C_*C_, bo, out);
}

// round 14
// speedup vs baseline: 1.0982x; 1.0154x over previous
#include <cuda_runtime.h>
#include <cuda_bf16.h>
#include <math.h>
#include <stdint.h>

#define B_      2
#define N_      4096
#define C_      256
#define H_      4
#define D_      64
#define MTOT    (B_*N_)        // 8192
// Q pre-scale: (1/8) * log2(e)  -> softmax numerator = exp2(S')
#define QSCALE_ 0.18033688011112042f
#define NSLICE  2
#define TILES_PER_SLICE 32

// Scratch (device globals; allocation-free)
__device__ __nv_bfloat16 g_whi[4][C_*C_], g_wlo[4][C_*C_];
__device__ __nv_bfloat16 g_qhi[MTOT*C_], g_qlo[MTOT*C_];   // [bh][n][d], Q pre-scaled
__device__ __nv_bfloat16 g_khi[MTOT*C_], g_klo[MTOT*C_];   // [bh][n][d]
__device__ __nv_bfloat16 g_vhi[MTOT*C_], g_vlo[MTOT*C_];   // [bh][n][d]
__device__ __nv_bfloat16 g_att[MTOT*C_];                   // [B*N][C] bf16 (exact)
__device__ float g_opart[512*NSLICE*64*64];                // unnormalized O partials
__device__ float g_lpart[512*NSLICE*64];                   // l partials

// ---------------------------------------------------------------------------
// helpers
// ---------------------------------------------------------------------------
__device__ __forceinline__ void mma_bf16(float c[4],
    uint32_t a0, uint32_t a1, uint32_t a2, uint32_t a3,
    uint32_t b0, uint32_t b1)
{
    asm volatile(
        "mma.sync.aligned.m16n8k16.row.col.f32.bf16.bf16.f32 "
        "{%0,%1,%2,%3}, {%4,%5,%6,%7}, {%8,%9}, {%0,%1,%2,%3};"
        : "+f"(c[0]), "+f"(c[1]), "+f"(c[2]), "+f"(c[3])
        : "r"(a0), "r"(a1), "r"(a2), "r"(a3), "r"(b0), "r"(b1));
}
__device__ __forceinline__ void ldmx4(uint32_t r[4], const void* p)
{
    uint32_t a = (uint32_t)__cvta_generic_to_shared(p);
    asm volatile("ldmatrix.sync.aligned.m8n8.x4.shared.b16 {%0,%1,%2,%3}, [%4];"
                 : "=r"(r[0]), "=r"(r[1]), "=r"(r[2]), "=r"(r[3]) : "r"(a));
}
__device__ __forceinline__ void ldmx4a(uint32_t r[4], uint32_t a)
{
    asm volatile("ldmatrix.sync.aligned.m8n8.x4.shared.b16 {%0,%1,%2,%3}, [%4];"
                 : "=r"(r[0]), "=r"(r[1]), "=r"(r[2]), "=r"(r[3]) : "r"(a));
}
__device__ __forceinline__ void ldmx4ta(uint32_t r[4], uint32_t a)
{
    asm volatile("ldmatrix.sync.aligned.m8n8.x4.trans.shared.b16 {%0,%1,%2,%3}, [%4];"
                 : "=r"(r[0]), "=r"(r[1]), "=r"(r[2]), "=r"(r[3]) : "r"(a));
}
__device__ __forceinline__ uint32_t pack_bf2(float a, float b)
{
    __nv_bfloat162 t = __floats2bfloat162_rn(a, b);
    return *(uint32_t*)&t;
}
__device__ __forceinline__ void cpa16(uint32_t dst, const void* src)
{
    asm volatile("cp.async.cg.shared.global [%0], [%1], 16;" :: "r"(dst), "l"(src));
}
__device__ __forceinline__ void cpa_commit()
{
    asm volatile("cp.async.commit_group;" ::: "memory");
}
template<int N>
__device__ __forceinline__ void cpa_wait()
{
    asm volatile("cp.async.wait_group %0;" :: "n"(N) : "memory");
}
__device__ __forceinline__ void split2(float a, float b, uint32_t& hi, uint32_t& lo)
{
    hi = pack_bf2(a, b);
    __nv_bfloat162 t = *(__nv_bfloat162*)&hi;
    float2 f = __bfloat1622float2(t);
    lo = pack_bf2(a - f.x, b - f.y);
}
__device__ __forceinline__ float ex2(float x)
{
    float r;
    asm("ex2.approx.f32 %0, %1;" : "=f"(r) : "f"(x));
    return r;
}

// ---------------------------------------------------------------------------
// split weights fp32 -> bf16 hi/lo (all 4 in one launch)
// ---------------------------------------------------------------------------
__global__ void split_w4(const float* __restrict__ w0, const float* __restrict__ w1,
                         const float* __restrict__ w2, const float* __restrict__ w3,
                         __nv_bfloat16* __restrict__ hi, __nv_bfloat16* __restrict__ lo)
{
    const int p = blockIdx.y;
    const float* src = (p == 0) ? w0 : (p == 1) ? w1 : (p == 2) ? w2 : w3;
    int i = blockIdx.x * blockDim.x + threadIdx.x;
    if (i >= C_*C_/4) return;
    float4 v = ((const float4*)src)[i];
    uint32_t h01, l01, h23, l23;
    split2(v.x, v.y, h01, l01);
    split2(v.z, v.w, h23, l23);
    ((uint2*)(hi + (size_t)p * C_ * C_))[i] = make_uint2(h01, h23);
    ((uint2*)(lo + (size_t)p * C_ * C_))[i] = make_uint2(l01, l23);
}

// ---------------------------------------------------------------------------
// Fused Q/K/V projection (3-term split bf16 MMA), NT. x clip+split inline.
// ---------------------------------------------------------------------------
#define GARR 4608   // elements per [64][72] array

__global__ __launch_bounds__(128, 3)
void gemm_qkv(const float* __restrict__ x,
              const __nv_bfloat16* __restrict__ Whi, const __nv_bfloat16* __restrict__ Wlo,
              const float* __restrict__ bq, const float* __restrict__ bk,
              const float* __restrict__ bv,
              __nv_bfloat16* __restrict__ qhi, __nv_bfloat16* __restrict__ qlo,
              __nv_bfloat16* __restrict__ khi, __nv_bfloat16* __restrict__ klo,
              __nv_bfloat16* __restrict__ vhi, __nv_bfloat16* __restrict__ vlo)
{
    extern __shared__ __align__(16) __nv_bfloat16 smg[];
    __nv_bfloat16* Ah = smg;
    __nv_bfloat16* Al = smg + GARR;

    const int tid  = threadIdx.x;
    const int lane = tid & 31;
    const int wid  = tid >> 5;
    const int wr   = wid * 16;
    const int m0   = blockIdx.x * 64;
    const int n0   = blockIdx.y * 64;

    const int grp = lane >> 3, rr = lane & 7;
    const int k_rofs = ((grp & 2) ? 8 : 0) + rr;
    const int k_cofs = (grp & 1) ? 8 : 0;

    float acc[3][8][4];
    #pragma unroll
    for (int p = 0; p < 3; p++)
        #pragma unroll
        for (int i = 0; i < 8; i++)
            { acc[p][i][0]=0.f; acc[p][i][1]=0.f; acc[p][i][2]=0.f; acc[p][i][3]=0.f; }

    for (int kt0 = 0; kt0 < 4; kt0++) {
        const int k0 = kt0 * 64;
        __syncthreads();
        #pragma unroll
        for (int it = 0; it < 4; it++) {
            const int idx = it * 128 + tid;
            const int r = idx >> 3, c8 = (idx & 7) * 8;
            {
                const float* xp = &x[(size_t)(m0 + r) * C_ + k0 + c8];
                float4 v0 = *(const float4*)xp;
                float4 v1 = *(const float4*)(xp + 4);
                v0.x = fminf(fmaxf(v0.x, -10000.f), 10000.f);
                v0.y = fminf(fmaxf(v0.y, -10000.f), 10000.f);
                v0.z = fminf(fmaxf(v0.z, -10000.f), 10000.f);
                v0.w = fminf(fmaxf(v0.w, -10000.f), 10000.f);
                v1.x = fminf(fmaxf(v1.x, -10000.f), 10000.f);
                v1.y = fminf(fmaxf(v1.y, -10000.f), 10000.f);
                v1.z = fminf(fmaxf(v1.z, -10000.f), 10000.f);
                v1.w = fminf(fmaxf(v1.w, -10000.f), 10000.f);
                uint32_t h0, l0, h1, l1, h2, l2, h3, l3;
                split2(v0.x, v0.y, h0, l0);
                split2(v0.z, v0.w, h1, l1);
                split2(v1.x, v1.y, h2, l2);
                split2(v1.z, v1.w, h3, l3);
                *(uint4*)&Ah[r * 72 + c8] = make_uint4(h0, h1, h2, h3);
                *(uint4*)&Al[r * 72 + c8] = make_uint4(l0, l1, l2, l3);
            }
            #pragma unroll
            for (int p = 0; p < 3; p++) {
                *(uint4*)&smg[(2+2*p)*GARR + r * 72 + c8] =
                    *(const uint4*)&Whi[(size_t)p * C_ * C_ + (size_t)(n0 + r) * C_ + k0 + c8];
                *(uint4*)&smg[(3+2*p)*GARR + r * 72 + c8] =
                    *(const uint4*)&Wlo[(size_t)p * C_ * C_ + (size_t)(n0 + r) * C_ + k0 + c8];
            }
        }
        __syncthreads();

        #pragma unroll
        for (int kt = 0; kt < 4; kt++) {
            uint32_t ah[4], al[4];
            ldmx4(ah, &Ah[(wr + (lane & 15)) * 72 + kt * 16 + (lane >> 4) * 8]);
            ldmx4(al, &Al[(wr + (lane & 15)) * 72 + kt * 16 + (lane >> 4) * 8]);
            #pragma unroll
            for (int p = 0; p < 3; p++) {
                const __nv_bfloat16* Bh = smg + (2+2*p)*GARR;
                const __nv_bfloat16* Bl = smg + (3+2*p)*GARR;
                #pragma unroll
                for (int jp = 0; jp < 4; jp++) {
                    uint32_t bh4[4], bl4[4];
                    ldmx4(bh4, Bh + (jp * 16 + k_rofs) * 72 + kt * 16 + k_cofs);
                    ldmx4(bl4, Bl + (jp * 16 + k_rofs) * 72 + kt * 16 + k_cofs);
                    mma_bf16(acc[p][2*jp],   ah[0], ah[1], ah[2], ah[3], bh4[0], bh4[1]);
                    mma_bf16(acc[p][2*jp+1], ah[0], ah[1], ah[2], ah[3], bh4[2], bh4[3]);
                    mma_bf16(acc[p][2*jp],   ah[0], ah[1], ah[2], ah[3], bl4[0], bl4[1]);
                    mma_bf16(acc[p][2*jp+1], ah[0], ah[1], ah[2], ah[3], bl4[2], bl4[3]);
                    mma_bf16(acc[p][2*jp],   al[0], al[1], al[2], al[3], bh4[0], bh4[1]);
                    mma_bf16(acc[p][2*jp+1], al[0], al[1], al[2], al[3], bh4[2], bh4[3]);
                }
            }
        }
    }

    const int g = lane >> 2, cc = (lane & 3) * 2;
    const int r0 = m0 + wr + g, r1 = r0 + 8;
    const int b0i = r0 >> 12, nl0 = r0 & 4095;
    const int b1i = r1 >> 12, nl1 = r1 & 4095;

    const float* biases[3] = {bq, bk, bv};
    __nv_bfloat16* ohis[3] = {qhi, khi, vhi};
    __nv_bfloat16* olos[3] = {qlo, klo, vlo};

    #pragma unroll
    for (int p = 0; p < 3; p++) {
        const float scale = (p == 0) ? QSCALE_ : 1.0f;
        #pragma unroll
        for (int jp = 0; jp < 4; jp++) {
            #pragma unroll
            for (int t = 0; t < 2; t++) {
                const int n = n0 + jp * 16 + t * 8 + cc;
                const float bb0 = __ldg(&biases[p][n]);
                const float bb1 = __ldg(&biases[p][n + 1]);
                float v00 = (acc[p][2*jp+t][0] + bb0) * scale;
                float v01 = (acc[p][2*jp+t][1] + bb1) * scale;
                float v10 = (acc[p][2*jp+t][2] + bb0) * scale;
                float v11 = (acc[p][2*jp+t][3] + bb1) * scale;
                const int h = n >> 6, d = n & 63;
                const size_t a0 = (((size_t)(b0i * H_ + h) * N_) + nl0) * D_ + d;
                const size_t a1 = (((size_t)(b1i * H_ + h) * N_) + nl1) * D_ + d;
                uint32_t h0, l0, h1, l1;
                split2(v00, v01, h0, l0);
                split2(v10, v11, h1, l1);
                *(uint32_t*)&ohis[p][a0] = h0;  *(uint32_t*)&olos[p][a0] = l0;
                *(uint32_t*)&ohis[p][a1] = h1;  *(uint32_t*)&olos[p][a1] = l1;
            }
        }
    }
}

// ---------------------------------------------------------------------------
// Out-projection GEMM (2-term; att exact bf16), cp.async double-buffered.
// smem: 2 buffers x {Ah,Bh,Bl}[64][72] = 55296 B dynamic.
// ---------------------------------------------------------------------------
#define OARR 4608        // elements per [64][72] array
#define OBUF (3*OARR)    // elements per buffer

__global__ __launch_bounds__(128, 4)
void gemm_out(const __nv_bfloat16* __restrict__ Ahi,
              const __nv_bfloat16* __restrict__ Bhi, const __nv_bfloat16* __restrict__ Blo,
              const float* __restrict__ bias, float* __restrict__ ofp)
{
    extern __shared__ __align__(16) __nv_bfloat16 smo[];

    const int tid  = threadIdx.x;
    const int lane = tid & 31;
    const int wid  = tid >> 5;
    const int wr   = wid * 16;
    const int m0   = blockIdx.x * 64;
    const int n0   = blockIdx.y * 64;

    const int grp = lane >> 3, rr = lane & 7;
    const int k_rofs = ((grp & 2) ? 8 : 0) + rr;
    const int k_cofs = (grp & 1) ? 8 : 0;

    // staging: each array 64x64 bf16 = 512 x 16B chunks; 128 thr x 4 chunks.
    // chunk idx: r = idx>>3 (row), c8 = (idx&7)*8 elements
    #define OSTAGE(bufbase, kk0)                                                   \
        {                                                                          \
            _Pragma("unroll")                                                      \
            for (int it = 0; it < 4; it++) {                                       \
                const int idx = it * 128 + tid;                                    \
                const int r = idx >> 3, c8 = (idx & 7) * 8;                        \
                const uint32_t so = (uint32_t)__cvta_generic_to_shared(            \
                                        smo + (bufbase)) + (uint32_t)(r * 144 + c8 * 2); \
                cpa16(so,               Ahi + (size_t)(m0 + r) * C_ + (kk0) + c8); \
                cpa16(so + OARR * 2,    Bhi + (size_t)(n0 + r) * C_ + (kk0) + c8); \
                cpa16(so + OARR * 4,    Blo + (size_t)(n0 + r) * C_ + (kk0) + c8); \
            }                                                                      \
        }

    float s[8][4];
    #pragma unroll
    for (int i = 0; i < 8; i++) { s[i][0]=0.f; s[i][1]=0.f; s[i][2]=0.f; s[i][3]=0.f; }

    OSTAGE(0, 0)
    cpa_commit();

    for (int kt0 = 0; kt0 < 4; kt0++) {
        if (kt0 > 0) __syncthreads();   // prior compute done with the other buffer
        if (kt0 + 1 < 4) OSTAGE(((kt0 + 1) & 1) * OBUF, (kt0 + 1) * 64)
        cpa_commit();
        cpa_wait<1>();                  // stage(kt0) complete
        __syncthreads();

        const __nv_bfloat16* Ah = smo + (kt0 & 1) * OBUF;
        const __nv_bfloat16* Bh = Ah + OARR;
        const __nv_bfloat16* Bl = Ah + 2 * OARR;

        #pragma unroll
        for (int kt = 0; kt < 4; kt++) {
            uint32_t ah[4];
            ldmx4(ah, Ah + (wr + (lane & 15)) * 72 + kt * 16 + (lane >> 4) * 8);
            #pragma unroll
            for (int jp = 0; jp < 4; jp++) {
                uint32_t bh4[4], bl4[4];
                ldmx4(bh4, Bh + (jp * 16 + k_rofs) * 72 + kt * 16 + k_cofs);
                ldmx4(bl4, Bl + (jp * 16 + k_rofs) * 72 + kt * 16 + k_cofs);
                mma_bf16(s[2*jp],   ah[0], ah[1], ah[2], ah[3], bh4[0], bh4[1]);
                mma_bf16(s[2*jp+1], ah[0], ah[1], ah[2], ah[3], bh4[2], bh4[3]);
                mma_bf16(s[2*jp],   ah[0], ah[1], ah[2], ah[3], bl4[0], bl4[1]);
                mma_bf16(s[2*jp+1], ah[0], ah[1], ah[2], ah[3], bl4[2], bl4[3]);
            }
        }
    }
    #undef OSTAGE

    const int g = lane >> 2, cc = (lane & 3) * 2;
    const int r0 = m0 + wr + g, r1 = r0 + 8;
    #pragma unroll
    for (int jp = 0; jp < 4; jp++) {
        #pragma unroll
        for (int t = 0; t < 2; t++) {
            const int n = n0 + jp * 16 + t * 8 + cc;
            const float b0 = __ldg(&bias[n]);
            const float b1 = __ldg(&bias[n + 1]);
            *(float2*)&ofp[(size_t)r0 * C_ + n] = make_float2(s[2*jp+t][0] + b0, s[2*jp+t][1] + b1);
            *(float2*)&ofp[(size_t)r1 * C_ + n] = make_float2(s[2*jp+t][2] + b0, s[2*jp+t][3] + b1);
        }
    }
}

// ---------------------------------------------------------------------------
// Flash attention v10 (NSLICE=2): flash5 inner loop, split-KV by 2 slices of
// 32 tiles (max-free softmax => purely additive partials). grid.z = slice.
// smem: K0h@0 K0l@8K K1h@16K K1l@24K Vh@32K Vl@40K = 48KB. 4 CTAs/SM.
// 1024 CTAs -> busiest SM 7x32 = 224 tiles (same as NSLICE=4, half overhead).
// ---------------------------------------------------------------------------
#define FK0   0u
#define FK1   16384u
#define FV    32768u
#define SMEM_F 49152

__global__ __launch_bounds__(128, 4)
void flash10(const __nv_bfloat16* __restrict__ qhi, const __nv_bfloat16* __restrict__ qlo,
             const __nv_bfloat16* __restrict__ khi, const __nv_bfloat16* __restrict__ klo,
             const __nv_bfloat16* __restrict__ vhi, const __nv_bfloat16* __restrict__ vlo,
             float* __restrict__ opart, float* __restrict__ lpart)
{
    extern __shared__ __align__(1024) char smf[];
    const uint32_t sb = (uint32_t)__cvta_generic_to_shared(smf);

    const int tid  = threadIdx.x;
    const int lane = tid & 31;
    const int wid  = tid >> 5;
    const int wr   = wid * 16;
    const int bh   = blockIdx.y;
    const int q0   = blockIdx.x * 64;
    const int slice = blockIdx.z;
    const int kt_beg = slice * TILES_PER_SLICE;
    const int kt_end = kt_beg + TILES_PER_SLICE;

    const char* kh_g = (const char*)(khi + (size_t)bh * N_ * D_);
    const char* kl_g = (const char*)(klo + (size_t)bh * N_ * D_);
    const char* vh_g = (const char*)(vhi + (size_t)bh * N_ * D_);
    const char* vl_g = (const char*)(vlo + (size_t)bh * N_ * D_);

    // staging geometry (algebraic SW128)
    const int st_r   = tid >> 3;
    const int st_c16 = (tid & 7) * 16;
    const uint32_t st_sc = (uint32_t)st_c16 ^ (((uint32_t)st_r & 7) << 4);

    // ---- prologue: groups {K(beg)}, {V(beg)}, {K(beg+1)} ----
    {
        const size_t tb0 = (size_t)kt_beg * 8192;
        #pragma unroll
        for (int it = 0; it < 4; it++) {
            const uint32_t off = (uint32_t)((st_r + it * 16) * 128 + st_c16);
            const uint32_t sw  = (uint32_t)((st_r + it * 16) * 128) + st_sc;
            cpa16(sb + FK0 + sw,        kh_g + tb0 + off);
            cpa16(sb + FK0 + 8192 + sw, kl_g + tb0 + off);
        }
        cpa_commit();
        #pragma unroll
        for (int it = 0; it < 4; it++) {
            const uint32_t off = (uint32_t)((st_r + it * 16) * 128 + st_c16);
            const uint32_t sw  = (uint32_t)((st_r + it * 16) * 128) + st_sc;
            cpa16(sb + FV + sw,        vh_g + tb0 + off);
            cpa16(sb + FV + 8192 + sw, vl_g + tb0 + off);
        }
        cpa_commit();
        #pragma unroll
        for (int it = 0; it < 4; it++) {
            const uint32_t off = (uint32_t)((st_r + it * 16) * 128 + st_c16);
            const uint32_t sw  = (uint32_t)((st_r + it * 16) * 128) + st_sc;
            cpa16(sb + FK1 + sw,        kh_g + tb0 + 8192 + off);
            cpa16(sb + FK1 + 8192 + sw, kl_g + tb0 + 8192 + off);
        }
        cpa_commit();
    }

    // Q fragments straight from gmem (Q pre-scaled by log2e/8, split)
    const int g  = lane >> 2;
    const int cc = (lane & 3) * 2;
    uint32_t qh[4][4], ql[4][4];
    {
        const size_t r0 = ((size_t)bh * N_ + q0 + wr + g) * D_;
        const size_t r1 = r0 + 8 * D_;
        #pragma unroll
        for (int kt = 0; kt < 4; kt++) {
            const int c = kt * 16 + cc;
            qh[kt][0] = *(const uint32_t*)&qhi[r0 + c];
            qh[kt][1] = *(const uint32_t*)&qhi[r1 + c];
            qh[kt][2] = *(const uint32_t*)&qhi[r0 + c + 8];
            qh[kt][3] = *(const uint32_t*)&qhi[r1 + c + 8];
            ql[kt][0] = *(const uint32_t*)&qlo[r0 + c];
            ql[kt][1] = *(const uint32_t*)&qlo[r1 + c];
            ql[kt][2] = *(const uint32_t*)&qlo[r0 + c + 8];
            ql[kt][3] = *(const uint32_t*)&qlo[r1 + c + 8];
        }
    }

    float o[8][4];
    #pragma unroll
    for (int i = 0; i < 8; i++) { o[i][0]=0.f; o[i][1]=0.f; o[i][2]=0.f; o[i][3]=0.f; }
    float l_g = 0.f, l_h = 0.f;

    // hoisted SW128 addressing: addr = base + R*128 + (col ^ (rr<<4))
    const int grp = lane >> 3, rr = lane & 7;
    const uint32_t xorv = (uint32_t)rr << 4;
    const uint32_t k_rowb = (uint32_t)((((grp & 2) ? 8 : 0) + rr) * 128);
    const uint32_t v_rowb = (uint32_t)((((grp & 1) ? 8 : 0) + rr) * 128);
    const uint32_t k_c2   = (grp & 1) ? 16u : 0u;
    const uint32_t v_c2   = (grp & 2) ? 16u : 0u;
    uint32_t colK[4], colV[4];
    #pragma unroll
    for (int i = 0; i < 4; i++) {
        colK[i] = ((uint32_t)(i * 32) + k_c2) ^ xorv;
        colV[i] = ((uint32_t)(i * 32) + v_c2) ^ xorv;
    }

    for (int kvt = kt_beg; kvt < kt_end; kvt++) {
        cpa_wait<1>();     // K(kvt) (2-tile lead) and V(kvt) (1-tile lead) ready
        __syncthreads();

        const uint32_t kb = sb + ((kvt & 1) ? FK1 : FK0) + k_rowb;
        const uint32_t vb = sb + FV + v_rowb;

        // ---- S = Q K^T (3-term) ----
        float s[8][4];
        #pragma unroll
        for (int i = 0; i < 8; i++) { s[i][0]=0.f; s[i][1]=0.f; s[i][2]=0.f; s[i][3]=0.f; }

        #pragma unroll
        for (int kt = 0; kt < 4; kt++) {
            #pragma unroll
            for (int jp = 0; jp < 4; jp++) {
                uint32_t bhr[4], blr[4];
                const uint32_t a = kb + (uint32_t)(jp * 2048) + colK[kt];
                ldmx4a(bhr, a);
                ldmx4a(blr, a + 8192);
                mma_bf16(s[2*jp],   qh[kt][0], qh[kt][1], qh[kt][2], qh[kt][3], bhr[0], bhr[1]);
                mma_bf16(s[2*jp+1], qh[kt][0], qh[kt][1], qh[kt][2], qh[kt][3], bhr[2], bhr[3]);
                mma_bf16(s[2*jp],   qh[kt][0], qh[kt][1], qh[kt][2], qh[kt][3], blr[0], blr[1]);
                mma_bf16(s[2*jp+1], qh[kt][0], qh[kt][1], qh[kt][2], qh[kt][3], blr[2], blr[3]);
                mma_bf16(s[2*jp],   ql[kt][0], ql[kt][1], ql[kt][2], ql[kt][3], bhr[0], bhr[1]);
                mma_bf16(s[2*jp+1], ql[kt][0], ql[kt][1], ql[kt][2], ql[kt][3], bhr[2], bhr[3]);
            }
        }

        // ---- max-free softmax: p = exp2(s') ----
        float sum_g = 0.f, sum_h = 0.f;
        #pragma unroll
        for (int nt = 0; nt < 8; nt++) {
            s[nt][0] = ex2(s[nt][0]);
            s[nt][1] = ex2(s[nt][1]);
            s[nt][2] = ex2(s[nt][2]);
            s[nt][3] = ex2(s[nt][3]);
            sum_g += s[nt][0] + s[nt][1];
            sum_h += s[nt][2] + s[nt][3];
        }
        l_g += sum_g;
        l_h += sum_h;

        // ---- O += P V (3-term, P frags in-register) ----
        #pragma unroll
        for (int kt = 0; kt < 4; kt++) {
            uint32_t pa0, pl0, pa1, pl1, pa2, pl2, pa3, pl3;
            split2(s[2*kt][0],   s[2*kt][1],   pa0, pl0);
            split2(s[2*kt][2],   s[2*kt][3],   pa1, pl1);
            split2(s[2*kt+1][0], s[2*kt+1][1], pa2, pl2);
            split2(s[2*kt+1][2], s[2*kt+1][3], pa3, pl3);

            #pragma unroll
            for (int dp = 0; dp < 4; dp++) {
                uint32_t vhr[4], vlr[4];
                const uint32_t a = vb + (uint32_t)(kt * 2048) + colV[dp];
                ldmx4ta(vhr, a);
                ldmx4ta(vlr, a + 8192);
                mma_bf16(o[2*dp],   pa0, pa1, pa2, pa3, vhr[0], vhr[1]);
                mma_bf16(o[2*dp+1], pa0, pa1, pa2, pa3, vhr[2], vhr[3]);
                mma_bf16(o[2*dp],   pa0, pa1, pa2, pa3, vlr[0], vlr[1]);
                mma_bf16(o[2*dp+1], pa0, pa1, pa2, pa3, vlr[2], vlr[3]);
                mma_bf16(o[2*dp],   pl0, pl1, pl2, pl3, vhr[0], vhr[1]);
                mma_bf16(o[2*dp+1], pl0, pl1, pl2, pl3, vhr[2], vhr[3]);
            }
        }

        __syncthreads();   // all warps done reading V(kvt) and K(kvt) buffers

        // issue group{V(kvt+1)} then group{K(kvt+2)} (empty groups keep count)
        if (kvt + 1 < kt_end) {
            const size_t tb = (size_t)(kvt + 1) * 8192;
            #pragma unroll
            for (int it = 0; it < 4; it++) {
                const uint32_t off = (uint32_t)((st_r + it * 16) * 128 + st_c16);
                const uint32_t sw  = (uint32_t)((st_r + it * 16) * 128) + st_sc;
                cpa16(sb + FV + sw,        vh_g + tb + off);
                cpa16(sb + FV + 8192 + sw, vl_g + tb + off);
            }
        }
        cpa_commit();
        if (kvt + 2 < kt_end) {
            const uint32_t kb2 = sb + ((kvt & 1) ? FK1 : FK0);
            const size_t tb = (size_t)(kvt + 2) * 8192;
            #pragma unroll
            for (int it = 0; it < 4; it++) {
                const uint32_t off = (uint32_t)((st_r + it * 16) * 128 + st_c16);
                const uint32_t sw  = (uint32_t)((st_r + it * 16) * 128) + st_sc;
                cpa16(kb2 + sw,        kh_g + tb + off);
                cpa16(kb2 + 8192 + sw, kl_g + tb + off);
            }
        }
        cpa_commit();
    }

    // l reduction (once)
    l_g += __shfl_xor_sync(0xffffffffu, l_g, 1);
    l_g += __shfl_xor_sync(0xffffffffu, l_g, 2);
    l_h += __shfl_xor_sync(0xffffffffu, l_h, 1);
    l_h += __shfl_xor_sync(0xffffffffu, l_h, 2);

    // ---- epilogue: write unnormalized f32 partial + l ----
    const int qindex = bh * 64 + blockIdx.x;                 // 0..511
    float* op = opart + ((size_t)(qindex * NSLICE + slice)) * 4096;
    float* lp = lpart + ((size_t)(qindex * NSLICE + slice)) * 64;
    const int rg = wr + g;        // local row 0..63
    const int rh = rg + 8;

    #pragma unroll
    for (int dt = 0; dt < 8; dt++) {
        const int col = dt * 8 + cc;
        *(float2*)&op[rg * 64 + col] = make_float2(o[dt][0], o[dt][1]);
        *(float2*)&op[rh * 64 + col] = make_float2(o[dt][2], o[dt][3]);
    }
    if ((lane & 3) == 0) {
        lp[rg] = l_g;
        lp[rh] = l_h;
    }
}

// ---------------------------------------------------------------------------
// Merge: att[row, col] = bf16( (sum_s O_s) / (sum_s l_s) )
// grid 512 (qindex), block 256: thread = (row = tid>>2, 16 cols).
// ---------------------------------------------------------------------------
__global__ __launch_bounds__(256)
void merge_att(const float* __restrict__ opart, const float* __restrict__ lpart,
               __nv_bfloat16* __restrict__ att)
{
    const int qindex = blockIdx.x;
    const int bh = qindex >> 6, qt = qindex & 63;
    const int b = bh >> 2, h = bh & 3;
    const int tid = threadIdx.x;
    const int r  = tid >> 2;
    const int cb = (tid & 3) * 16;

    const float* op = opart + (size_t)(qindex * NSLICE) * 4096;
    const float* lp = lpart + (size_t)(qindex * NSLICE) * 64;

    float l = lp[r] + lp[64 + r];
    const float inv = 1.f / l;

    uint32_t w[8];
    #pragma unroll
    for (int c4 = 0; c4 < 4; c4++) {
        const int ofs = r * 64 + cb + c4 * 4;
        float4 a0 = *(const float4*)&op[ofs];
        float4 a1 = *(const float4*)&op[4096 + ofs];
        float x0 = (a0.x + a1.x) * inv;
        float x1 = (a0.y + a1.y) * inv;
        float x2 = (a0.z + a1.z) * inv;
        float x3 = (a0.w + a1.w) * inv;
        w[c4*2]   = pack_bf2(x0, x1);
        w[c4*2+1] = pack_bf2(x2, x3);
    }
    __nv_bfloat16* dst = att + (size_t)(b * N_ + qt * 64 + r) * C_ + h * D_ + cb;
    *(uint4*)dst       = make_uint4(w[0], w[1], w[2], w[3]);
    *(uint4*)(dst + 8) = make_uint4(w[4], w[5], w[6], w[7]);
}

// ---------------------------------------------------------------------------
extern "C" void kernel_launch(void* const* d_in, const int* in_sizes, int n_in,
                              void* d_out, int out_size)
{
    (void)in_sizes; (void)n_in; (void)out_size;
    const float* x  = (const float*)d_in[0];
    const float* Wq = (const float*)d_in[1];
    const float* bq = (const float*)d_in[2];
    const float* Wk = (const float*)d_in[3];
    const float* bk = (const float*)d_in[4];
    const float* Wv = (const float*)d_in[5];
    const float* bv = (const float*)d_in[6];
    const float* Wo = (const float*)d_in[7];
    const float* bo = (const float*)d_in[8];
    float* out = (float*)d_out;

    __nv_bfloat16 *whi, *wlo, *qhi, *qlo, *khi, *klo, *vhi, *vlo, *att;
    float *opart, *lpart;
    cudaGetSymbolAddress((void**)&whi, g_whi);
    cudaGetSymbolAddress((void**)&wlo, g_wlo);
    cudaGetSymbolAddress((void**)&qhi, g_qhi);
    cudaGetSymbolAddress((void**)&qlo, g_qlo);
    cudaGetSymbolAddress((void**)&khi, g_khi);
    cudaGetSymbolAddress((void**)&klo, g_klo);
    cudaGetSymbolAddress((void**)&vhi, g_vhi);
    cudaGetSymbolAddress((void**)&vlo, g_vlo);
    cudaGetSymbolAddress((void**)&att, g_att);
    cudaGetSymbolAddress((void**)&opart, g_opart);
    cudaGetSymbolAddress((void**)&lpart, g_lpart);

    split_w4<<<dim3((C_*C_/4 + 255)/256, 4), 256>>>(Wq, Wk, Wv, Wo, whi, wlo);

    cudaFuncSetAttribute(gemm_qkv, cudaFuncAttributeMaxDynamicSharedMemorySize, 8*GARR*2);
    dim3 gGrid(MTOT / 64, C_ / 64);
    gemm_qkv<<<gGrid, 128, 8*GARR*2>>>(x, whi, wlo, bq, bk, bv,
                                       qhi, qlo, khi, klo, vhi, vlo);

    cudaFuncSetAttribute(flash10, cudaFuncAttributeMaxDynamicSharedMemorySize, SMEM_F);
    dim3 fGrid(N_ / 64, B_ * H_, NSLICE);
    flash10<<<fGrid, 128, SMEM_F>>>(qhi, qlo, khi, klo, vhi, vlo, opart, lpart);

    merge_att<<<512, 256>>>(opart, lpart, att);

    cudaFuncSetAttribute(gemm_out, cudaFuncAttributeMaxDynamicSharedMemorySize, 2*OBUF*2);
    gemm_out<<<gGrid, 128, 2*OBUF*2>>>(att, whi + 3*C_*C_, wlo + 3*C_*C_, bo, out);
}